// round 5
// baseline (speedup 1.0000x reference)
#include <cuda_runtime.h>
#include <cstdint>

#define B_   32
#define CI   256
#define COUT 256
#define Hs   56
#define Ws   56
#define HW   3136
#define NPOS 100352      // B_*HW
#define TOT  25690112    // B_*COUT*HW
#define NT   784         // pixel tiles of 128

// ---------------- device scratch ----------------
__device__ int8_t             g_Xs[(size_t)B_ * 58 * 58 * 256];  // s8 sign acts, padded, channel-last
__device__ int8_t             g_Wb[9 * 256 * 256];               // s8 sign weights [tap][co][ci]
__device__ float              g_alpha[COUT];
__device__ int                g_sumS[COUT];
__device__ unsigned long long g_sumSq[COUT];
__device__ short              g_S[TOT];                          // exact conv ints, [co][pixel]
__device__ int                g_ti[COUT];
__device__ int                g_mode[COUT];

// ---------------- ptx helpers ----------------
__device__ __forceinline__ uint32_t s2u(const void* p) {
    uint32_t a;
    asm("{ .reg .u64 t; cvta.to.shared.u64 t, %1; cvt.u32.u64 %0, t; }" : "=r"(a) : "l"(p));
    return a;
}
__device__ __forceinline__ void cpa16(uint32_t s, const void* g) {
    asm volatile("cp.async.cg.shared.global [%0], [%1], 16;" :: "r"(s), "l"(g));
}
#define CP_COMMIT() asm volatile("cp.async.commit_group;" ::: "memory")
#define CP_WAIT1()  asm volatile("cp.async.wait_group 1;" ::: "memory")
#define CP_WAIT0()  asm volatile("cp.async.wait_group 0;" ::: "memory")

__device__ __forceinline__ void ldm4(uint32_t* r, uint32_t a) {
    asm volatile("ldmatrix.sync.aligned.m8n8.x4.shared.b16 {%0,%1,%2,%3}, [%4];"
                 : "=r"(r[0]), "=r"(r[1]), "=r"(r[2]), "=r"(r[3]) : "r"(a));
}
__device__ __forceinline__ void imma(int* d, const uint32_t* a, uint32_t b0, uint32_t b1) {
    asm volatile(
        "mma.sync.aligned.m16n8k32.row.col.s32.s8.s8.s32 "
        "{%0,%1,%2,%3}, {%4,%5,%6,%7}, {%8,%9}, {%0,%1,%2,%3};"
        : "+r"(d[0]), "+r"(d[1]), "+r"(d[2]), "+r"(d[3])
        : "r"(a[0]), "r"(a[1]), "r"(a[2]), "r"(a[3]), "r"(b0), "r"(b1));
}

// ---------------- kernel 0: zero stats ----------------
__global__ void k_zero() {
    int t = threadIdx.x;
    g_sumS[t] = 0;
    g_sumSq[t] = 0ULL;
}

// ---------------- kernel 1: sign + transpose to channel-last padded s8 -----
__global__ void k_signT(const float* __restrict__ x) {
    __shared__ int8_t s[256][57];
    int h = blockIdx.x, b = blockIdx.y;
    const float* xp = x + (size_t)b * CI * HW + (size_t)h * Ws;
    for (int idx = threadIdx.x; idx < 256 * 56; idx += 256) {
        int ci = idx / 56, w = idx - ci * 56;
        float v = xp[(size_t)ci * HW + w];
        s[ci][w] = (v > 0.0f) ? (int8_t)1 : (int8_t)-1;
    }
    __syncthreads();
    int8_t* outp = g_Xs + (((size_t)b * 58 + h + 1) * 58 + 1) * 256;
    for (int idx = threadIdx.x; idx < 256 * 56; idx += 256) {
        int w = idx >> 8, ci = idx & 255;
        outp[(size_t)w * 256 + ci] = s[ci][w];
    }
}

// ---------------- kernel 1b: zero padded border ----------------
__global__ void k_border() {
    int b = blockIdx.x;
    uint4 z = make_uint4(0, 0, 0, 0);
    uint4* base = (uint4*)g_Xs;
    for (int i = threadIdx.x; i < 228 * 16; i += 256) {
        int e = i >> 4, q = i & 15;
        int hh, ww;
        if (e < 58)       { hh = 0;           ww = e; }
        else if (e < 116) { hh = 57;          ww = e - 58; }
        else if (e < 172) { hh = e - 116 + 1; ww = 0; }
        else              { hh = e - 172 + 1; ww = 57; }
        base[(((size_t)b * 58 + hh) * 58 + ww) * 16 + q] = z;
    }
}

// ---------------- kernel 2: weight prep ----------------
__global__ void k_wprep(const float* __restrict__ wgt) {
    int co = blockIdx.x;
    int ci = threadIdx.x;
    int lane = ci & 31, warp = ci >> 5;

    __shared__ double smp[8][9];
    __shared__ double smean[9];
    __shared__ float sal[8];

    float wv[9];
    const float* wp = wgt + ((size_t)co * CI + ci) * 9;
#pragma unroll
    for (int k = 0; k < 9; k++) wv[k] = wp[k];

#pragma unroll
    for (int k = 0; k < 9; k++) {
        double v = (double)wv[k];
        for (int o = 16; o; o >>= 1) v += __shfl_xor_sync(0xffffffffu, v, o);
        if (lane == 0) smp[warp][k] = v;
    }
    __syncthreads();
    if (ci < 9) {
        double s = 0.0;
        for (int w = 0; w < 8; w++) s += smp[w][ci];
        smean[ci] = s * (1.0 / 256.0);
    }
    __syncthreads();

    float asum = 0.0f;
#pragma unroll
    for (int k = 0; k < 9; k++) {
        double wcd = (double)wv[k] - smean[k];
        float wc = (float)wcd;
        wc = fminf(fmaxf(wc, -1.0f), 1.0f);
        asum += fabsf(wc);
        g_Wb[((size_t)k * 256 + co) * 256 + ci] = (wcd > 0.0) ? (int8_t)1 : (int8_t)-1;
    }
    for (int o = 16; o; o >>= 1) asum += __shfl_xor_sync(0xffffffffu, asum, o);
    if (lane == 0) sal[warp] = asum;
    __syncthreads();
    if (ci == 0) {
        float t = 0.0f;
        for (int w = 0; w < 8; w++) t += sal[w];
        g_alpha[co] = t * (1.0f / 2304.0f);
    }
}

// ---------------- kernel 3: IMMA implicit conv ----------------
// grid (784 ntiles, 2 mtiles), 256 threads (8 warps, 2m x 4n), warp tile 64x32.
// SMEM per buffer 16KB: A s8 [chunk0..3][row0..127][16B] @0, B same @8192.
__global__ void __launch_bounds__(256, 2) k_conv() {
    __shared__ char smem[32768];
    const uint32_t sa = s2u(smem);
    const int tid = threadIdx.x;
    const int lane = tid & 31, wp = tid >> 5;
    const int wm = wp >> 2, wn = wp & 3;
    const int m0 = (int)blockIdx.y << 7;
    const int n0 = (int)blockIdx.x << 7;

    // per-thread load meta
    const int row2 = tid >> 1, hf = tid & 1;
    {
    }
    int P = n0 + row2;
    int b = P / HW, hw = P - b * HW;
    int h = hw / Ws, w = hw - h * Ws;
    const int8_t* xb = g_Xs + (((size_t)b * 58 + h) * 58 + w) * 256 + hf * 32;
    const int8_t* wb0 = g_Wb + ((size_t)(m0 + row2)) * 256 + hf * 32;
    const uint32_t aoff = (uint32_t)(2 * hf) * 2048 + row2 * 16;
    const uint32_t boff = 8192 + aoff;

    // frag address meta
    const int g8 = lane >> 3, lr = lane & 7;
    const int arowb = wm * 64 + lr + ((g8 & 1) << 3);
    const int achk  = g8 >> 1;
    const int browb = wn * 32 + lr + ((g8 >> 1) << 3);
    const int bchk  = g8 & 1;

    int d[4][4][4];
#pragma unroll
    for (int i = 0; i < 4; i++)
#pragma unroll
        for (int j = 0; j < 4; j++)
#pragma unroll
            for (int c = 0; c < 4; c++) d[i][j][c] = 0;

#define ISSUE(S) do {                                                        \
        int _s = (S);                                                        \
        int _t = _s >> 2, _kc = _s & 3;                                      \
        int _kh = _t / 3, _kw = _t - _kh * 3;                                \
        uint32_t _bo = (uint32_t)(_s & 1) * 16384;                           \
        const int8_t* _ws = wb0 + _t * 65536 + _kc * 64;                     \
        cpa16(sa + _bo + aoff, _ws);                                         \
        cpa16(sa + _bo + aoff + 2048, _ws + 16);                             \
        const int8_t* _xs = xb + (_kh * 58 + _kw) * 256 + _kc * 64;          \
        cpa16(sa + _bo + boff, _xs);                                         \
        cpa16(sa + _bo + boff + 2048, _xs + 16);                             \
        CP_COMMIT();                                                         \
    } while (0)

    ISSUE(0);

#pragma unroll 1
    for (int s = 0; s < 36; s++) {
        if (s < 35) { ISSUE(s + 1); CP_WAIT1(); }
        else        { CP_WAIT0(); }
        __syncthreads();

        uint32_t bufo = (uint32_t)(s & 1) * 16384;
#pragma unroll
        for (int kc32 = 0; kc32 < 2; kc32++) {
            int c0 = kc32 * 2;
            uint32_t af[4][4], bf[2][4];
#pragma unroll
            for (int im = 0; im < 4; im++)
                ldm4(af[im], sa + bufo + (uint32_t)(c0 + achk) * 2048
                              + (uint32_t)(arowb + im * 16) * 16);
#pragma unroll
            for (int in2 = 0; in2 < 2; in2++)
                ldm4(bf[in2], sa + bufo + 8192 + (uint32_t)(c0 + bchk) * 2048
                               + (uint32_t)(browb + in2 * 16) * 16);
#pragma unroll
            for (int im = 0; im < 4; im++)
#pragma unroll
                for (int in = 0; in < 4; in++)
                    imma(d[im][in], af[im], bf[in >> 1][(in & 1) * 2],
                         bf[in >> 1][(in & 1) * 2 + 1]);
        }
        __syncthreads();
    }

    // ---- epilogue: stage s16 tile in smem (128 rows x 128 cols) ----
#pragma unroll
    for (int im = 0; im < 4; im++)
#pragma unroll
        for (int in = 0; in < 4; in++) {
            int r0  = wm * 64 + im * 16 + (lane >> 2);
            int col = wn * 32 + in * 8 + 2 * (lane & 3);
            uint32_t p0 = (uint32_t)(uint16_t)d[im][in][0]
                        | ((uint32_t)(uint16_t)d[im][in][1] << 16);
            uint32_t p1 = (uint32_t)(uint16_t)d[im][in][2]
                        | ((uint32_t)(uint16_t)d[im][in][3] << 16);
            *(uint32_t*)(smem + r0 * 256 + col * 2)       = p0;
            *(uint32_t*)(smem + (r0 + 8) * 256 + col * 2) = p1;
        }
    __syncthreads();

    // ---- stats + coalesced global store ----
    {
        int row = tid >> 1, hn = tid & 1;
        const short* sp = (const short*)(smem + row * 256 + hn * 128);
        int sum = 0;
        long long sq = 0;
#pragma unroll
        for (int i = 0; i < 64; i++) {
            int v = sp[i];
            sum += v;
            sq  += (long long)(v * v);
        }
        uint4* dst = (uint4*)&g_S[(size_t)(m0 + row) * NPOS + n0 + hn * 64];
        const uint4* s4 = (const uint4*)sp;
#pragma unroll
        for (int i = 0; i < 8; i++) dst[i] = s4[i];

        sum += __shfl_xor_sync(0xffffffffu, sum, 1);
        sq  += __shfl_xor_sync(0xffffffffu, sq, 1);
        if (hn == 0) {
            atomicAdd(&g_sumS[m0 + row], sum);
            atomicAdd(&g_sumSq[m0 + row], (unsigned long long)sq);
        }
    }
#undef ISSUE
}

// ---------------- kernel 4: per-channel integer threshold ----------------
__global__ void k_thresh(const float* __restrict__ gamma,
                         const float* __restrict__ beta) {
    int co = threadIdx.x;
    double M      = (double)NPOS;
    double mean_s = (double)g_sumS[co] / M;
    double var_s  = (double)g_sumSq[co] / M - mean_s * mean_s;
    double al     = (double)g_alpha[co];
    double inv    = 1.0 / sqrt(al * al * var_s + 1e-5);
    double scale  = (double)gamma[co] * al * inv;
    double be     = (double)beta[co];

    int mode;
    int ti = 0;
    if (scale > 0.0) {
        mode = 1;
        double t = mean_s - be / scale;
        t = fmin(fmax(t, -1.0e7), 1.0e7);
        ti = (int)floor(t) + 1;
    } else if (scale < 0.0) {
        mode = -1;
        double t = mean_s - be / scale;
        t = fmin(fmax(t, -1.0e7), 1.0e7);
        ti = (int)ceil(t) - 1;
    } else {
        mode = (be > 0.0) ? 2 : 0;
    }
    g_ti[co]   = ti;
    g_mode[co] = mode;
}

// ---------------- kernel 5: threshold map -> float {0,1} ----------------
__global__ void k_pass2(float* __restrict__ out) {
    int i     = blockIdx.x * blockDim.x + threadIdx.x;
    int base  = i * 8;
    int b     = base / (COUT * HW);
    int rem   = base - b * (COUT * HW);
    int co    = rem / HW;
    int hw    = rem - co * HW;

    int ti   = g_ti[co];
    int mode = g_mode[co];
    uint4 raw = *(const uint4*)&g_S[(size_t)co * NPOS + b * HW + hw];
    const short* s = (const short*)&raw;
    float o[8];
    if (mode == 1) {
#pragma unroll
        for (int k = 0; k < 8; k++) o[k] = (s[k] >= ti) ? 1.0f : 0.0f;
    } else if (mode == -1) {
#pragma unroll
        for (int k = 0; k < 8; k++) o[k] = (s[k] <= ti) ? 1.0f : 0.0f;
    } else {
        float cst = (mode == 2) ? 1.0f : 0.0f;
#pragma unroll
        for (int k = 0; k < 8; k++) o[k] = cst;
    }
    float4* op = (float4*)&out[(size_t)base];
    op[0] = make_float4(o[0], o[1], o[2], o[3]);
    op[1] = make_float4(o[4], o[5], o[6], o[7]);
}

// ---------------- launch ----------------
extern "C" void kernel_launch(void* const* d_in, const int* in_sizes, int n_in,
                              void* d_out, int out_size) {
    const float* x     = (const float*)d_in[0];
    const float* wgt   = (const float*)d_in[1];
    const float* gamma = (const float*)d_in[3];
    const float* beta  = (const float*)d_in[4];
    float* out = (float*)d_out;

    k_zero  <<<1, 256>>>();
    k_signT <<<dim3(56, 32), 256>>>(x);
    k_border<<<32, 256>>>();
    k_wprep <<<256, 256>>>(wgt);
    k_conv  <<<dim3(NT, 2), 256>>>();
    k_thresh<<<1, 256>>>(gamma, beta);
    k_pass2 <<<TOT / 8 / 256, 256>>>(out);
}